// round 17
// baseline (speedup 1.0000x reference)
#include <cuda_runtime.h>
#include <cuda_fp16.h>
#include <mma.h>

using namespace nvcuda;

// Problem constants
#define B_    8
#define C_    64
#define CP_   80    // padded c: 64 real + 1 bias channel + 15 zero (5 k-tiles of 16)
#define N_    4096
#define K_    16
#define OUT_  64
#define R_    128   // 2*OUT rows: [0,64) = u (=(W1-W2)x + bias), [64,128) = v (=W2 x)

#define NT_   128            // nodes per gemm block tile
#define LDA   136            // sA: half[CP_][LDA]   ([c][n], n padded)
#define LDBT  80             // sBt: half[R_][LDBT]  ([r][c], c padded to 80)
#define LDSC  136            // scratch: half[NT_][LDSC]
#define SA_BYTES  (CP_ * LDA * 2)           // 21,760
#define SBT_BYTES (R_ * LDBT * 2)           // 20,480
#define SMEM_BYTES (SA_BYTES + SBT_BYTES)   // 42,240 (< 48KB; scratch 34,816 unions inside)

// Scratch (device global — no allocation allowed)
__device__ __half g_uvh[B_ * N_ * R_];   // [b][n][r] half: row = 256B = [u 0..63 | v 0..63]

__device__ __forceinline__ uint2 half4_pack(float a, float b, float c, float d) {
    uint2 r;
    __half2 h0 = __floats2half2_rn(a, b);
    __half2 h1 = __floats2half2_rn(c, d);
    r.x = *(unsigned*)&h0;
    r.y = *(unsigned*)&h1;
    return r;
}

// ---------------------------------------------------------------------------
// Kernel 1 (HMMA, fp16 accumulate): uv[n][r] = sum_c x[c][n]*Wt[c][r],
// bias folded as channel c=64. All smem staging vectorized (LDG.128/STS.64):
//   A = x^T col_major -> sA[c][n]  (x natural; float4 in, half4 out)
//   B        col_major -> sBt[r][c] (c contiguous: transform reads W rows as
//                                    float4 and writes u/v rows as half4)
// Fragment stores bounce via half scratch; uint4 copy epilogue.
// Block 256 thr (8 warps), tile 128n x 128r; warp = 16n x 128r, 5 k-tiles.
// ---------------------------------------------------------------------------
__global__ void __launch_bounds__(256) gemm_uv(const float* __restrict__ x,
                                               const float* __restrict__ W,
                                               const float* __restrict__ bias) {
    extern __shared__ char dyn[];
    __half* sA  = (__half*)dyn;                 // [CP_][LDA]
    __half* sBt = (__half*)(dyn + SA_BYTES);    // [R_][LDBT]
    __half* sc  = (__half*)dyn;                 // [NT_][LDSC] (union, after sync)

    const int b  = blockIdx.y;
    const int n0 = blockIdx.x * NT_;
    const int t  = threadIdx.x;
    const int wp = t >> 5;        // warp id = 16-node subtile (8 of them)

    // ---- sA[c][n] fill: 80 c-rows x 32 n-quads = 2560 quads, 10 iters
    for (int lin = t; lin < CP_ * (NT_ / 4); lin += 256) {
        int c  = lin >> 5;
        int nq = (lin & 31) * 4;
        uint2 h;
        if (c < 64) {
            const float4 v = *(const float4*)&x[((b * C_ + c) * N_) + n0 + nq];
            h = half4_pack(v.x, v.y, v.z, v.w);
        } else if (c == 64) {
            h = half4_pack(1.0f, 1.0f, 1.0f, 1.0f);
        } else {
            h.x = 0u; h.y = 0u;
        }
        *(uint2*)(sA + c * LDA + nq) = h;
    }

    // ---- sBt[r][c] fill (c<64): 64 r x 16 c-quads = 1024 quads, 4 iters
    // u row r: W1[r][c]-W2[r][c];  v row r+64: W2[r][c]
    for (int lin = t; lin < OUT_ * 16; lin += 256) {
        int r  = lin >> 4;
        int cq = (lin & 15) * 4;
        const float4 a = *(const float4*)&W[r * 128 + cq];        // W1[r][c..c+3]
        const float4 v = *(const float4*)&W[r * 128 + 64 + cq];   // W2[r][c..c+3]
        *(uint2*)(sBt + r * LDBT + cq)          = half4_pack(a.x - v.x, a.y - v.y, a.z - v.z, a.w - v.w);
        *(uint2*)(sBt + (r + 64) * LDBT + cq)   = half4_pack(v.x, v.y, v.z, v.w);
    }
    // ---- sBt pad columns c=64..79: bias at c=64 of u rows, zeros elsewhere
    for (int lin = t; lin < R_ * 4; lin += 256) {   // 128 r x 4 quads
        int r  = lin >> 2;
        int cq = 64 + (lin & 3) * 4;
        uint2 h;
        if (r < 64 && cq == 64) h = half4_pack(bias[r], 0.0f, 0.0f, 0.0f);
        else                    { h.x = 0u; h.y = 0u; }
        *(uint2*)(sBt + r * LDBT + cq) = h;
    }
    __syncthreads();

    // ---- MMA: warp wp computes nodes [wp*16, wp*16+16) x 128 r, 5 k-tiles
    wmma::fragment<wmma::matrix_a, 16, 16, 16, __half, wmma::col_major> fa[5];
    #pragma unroll
    for (int k = 0; k < 5; k++)
        wmma::load_matrix_sync(fa[k], sA + (k * 16) * LDA + wp * 16, LDA);

    wmma::fragment<wmma::accumulator, 16, 16, 16, __half> fc[8];
    #pragma unroll
    for (int rt = 0; rt < 8; rt++) {
        wmma::fill_fragment(fc[rt], __float2half(0.0f));
        #pragma unroll
        for (int k = 0; k < 5; k++) {
            // B col_major: element (k,n) at n*ldm + k -> layout [r][c], ldm=LDBT
            wmma::fragment<wmma::matrix_b, 16, 16, 16, __half, wmma::col_major> fb;
            wmma::load_matrix_sync(fb, sBt + (rt * 16) * LDBT + k * 16, LDBT);
            wmma::mma_sync(fc[rt], fa[k], fb, fc[rt]);
        }
    }
    __syncthreads();   // all warps done reading sA/sBt before scratch overwrite

    #pragma unroll
    for (int rt = 0; rt < 8; rt++)
        wmma::store_matrix_sync(sc + (wp * 16) * LDSC + rt * 16, fc[rt],
                                LDSC, wmma::mem_row_major);
    __syncthreads();

    // ---- epilogue: pure uint4 copy, 256B contiguous per node in gmem
    __half* outb = g_uvh + (size_t)(b * N_ + n0) * R_;
    for (int idx = t; idx < NT_ * 16; idx += 256) {   // 16 uint4 per node row
        int nl = idx >> 4;
        int q  = idx & 15;
        uint4 v = *(const uint4*)(sc + nl * LDSC + q * 8);
        *(uint4*)(outb + nl * R_ + q * 8) = v;
    }
}

// ---------------------------------------------------------------------------
// Kernel 2: out[b][o][n] = max_k relu( u[b][i1(k)][o] + v[b][i0(k)][o] )
// 4 nodes per warp, 8 lanes/node, LDG.128 gathers, half2 add/max.
// Indices staged PRE-SCALED (i1*128 / i0*128+64, in half units) via int4 edge
// loads -> per-kk addressing is a single add, no IMAD.
// ---------------------------------------------------------------------------
__global__ void __launch_bounds__(256) gather_max(const int* __restrict__ edge,
                                                  float* __restrict__ out) {
    __shared__ int2  sIdx[32][17];   // [node_local][k] (v_off, u_off); padded
    __shared__ float sm[OUT_][33];   // transpose stage, pad 32->33

    const int b  = blockIdx.y;
    const int n0 = blockIdx.x * 32;
    const int t  = threadIdx.x;

    // Stage indices: 32 nodes x 4 k-quads, int4 loads, prescaled offsets.
    for (int lin = t; lin < 128; lin += 256) {
        int node = lin >> 2;
        int kq   = (lin & 3) * 4;
        const int4 a = *(const int4*)&edge[((0 * B_ + b) * N_ + n0 + node) * K_ + kq]; // i0 -> v
        const int4 c = *(const int4*)&edge[((1 * B_ + b) * N_ + n0 + node) * K_ + kq]; // i1 -> u
        sIdx[node][kq + 0] = make_int2(((a.x & (N_ - 1)) << 7) + 64, (c.x & (N_ - 1)) << 7);
        sIdx[node][kq + 1] = make_int2(((a.y & (N_ - 1)) << 7) + 64, (c.y & (N_ - 1)) << 7);
        sIdx[node][kq + 2] = make_int2(((a.z & (N_ - 1)) << 7) + 64, (c.z & (N_ - 1)) << 7);
        sIdx[node][kq + 3] = make_int2(((a.w & (N_ - 1)) << 7) + 64, (c.w & (N_ - 1)) << 7);
    }
    __syncthreads();

    const int w    = t >> 5;
    const int lane = t & 31;
    const int h    = lane >> 3;          // node slot 0..3
    const int sl   = lane & 7;           // channel group: halves [8*sl, 8*sl+8)
    const int nl   = 4 * w + h;          // node local 0..31

    const __half* uvb = g_uvh + (size_t)b * N_ * R_;
    const int co = 8 * sl;

    __half2 m0 = __float2half2_rn(0.0f);
    __half2 m1 = m0, m2 = m0, m3 = m0;

    #pragma unroll
    for (int kk = 0; kk < K_; kk++) {
        int2 p = sIdx[nl][kk];           // broadcast within 8-lane group
        uint4 uu = *(const uint4*)(uvb + p.y + co);   // u[co..co+7] of center
        uint4 vv = *(const uint4*)(uvb + p.x + co);   // v[co..co+7] of neighbor
        m0 = __hmax2(m0, __hadd2(*(__half2*)&uu.x, *(__half2*)&vv.x));
        m1 = __hmax2(m1, __hadd2(*(__half2*)&uu.y, *(__half2*)&vv.y));
        m2 = __hmax2(m2, __hadd2(*(__half2*)&uu.z, *(__half2*)&vv.z));
        m3 = __hmax2(m3, __hadd2(*(__half2*)&uu.w, *(__half2*)&vv.w));
    }

    // Transpose stage: lane owns channels co..co+7 of node nl.
    float2 f;
    f = __half22float2(m0); sm[co + 0][nl] = f.x; sm[co + 1][nl] = f.y;
    f = __half22float2(m1); sm[co + 2][nl] = f.x; sm[co + 3][nl] = f.y;
    f = __half22float2(m2); sm[co + 4][nl] = f.x; sm[co + 5][nl] = f.y;
    f = __half22float2(m3); sm[co + 6][nl] = f.x; sm[co + 7][nl] = f.y;
    __syncthreads();

    #pragma unroll
    for (int it = 0; it < 8; it++) {
        int lin = t + it * 256;          // 2048 values: 64 o x 32 n
        int o   = lin >> 5;
        int nn  = lin & 31;
        out[((b * OUT_ + o) * N_) + n0 + nn] = sm[o][nn];
    }
}

// ---------------------------------------------------------------------------
extern "C" void kernel_launch(void* const* d_in, const int* in_sizes, int n_in,
                              void* d_out, int out_size) {
    const float* x    = (const float*)d_in[0];
    const int*   edge = (const int*)d_in[1];
    const float* W    = (const float*)d_in[2];
    const float* bias = (const float*)d_in[3];
    float*       out  = (float*)d_out;

    dim3 g1(N_ / NT_, B_);
    gemm_uv<<<g1, 256, SMEM_BYTES>>>(x, W, bias);

    dim3 g2(N_ / 32, B_);
    gather_max<<<g2, 256>>>(edge, out);
}